// round 13
// baseline (speedup 1.0000x reference)
#include <cuda_runtime.h>
#include <cstdint>

// SVD predict: R2 register-gather + smem-staged per-warp TMA bulk feature store.
// Moves 2KB/warp of feature stores off the L1tex wavefront queue (STG.128 ->
// STS + cp.async.bulk smem->global). Warp-autonomous, no CTA barriers.
//
// Inputs (metadata order):
//   d_in[0] user_item  int32  [131072, 2]
//   d_in[1] pu         f32    [1000000, 64]
//   d_in[2] qi         f32    [500000, 64]
//   d_in[3] bu         f32    [1000000]
//   d_in[4] bi         f32    [500000]
//   d_in[5] global_mean f32   [1]
// Output: float32 [131072 predict] ++ [131072 x 128 features]

#define BATCH 131072
#define ROWS_PER_WARP 4
#define WARPS_PER_CTA 8
#define THREADS 256
#define ROW_FLOATS 128                       // [p(64) | q(64)]
#define WARP_TILE_FLOATS (ROWS_PER_WARP * ROW_FLOATS)   // 512 floats = 2 KB

__device__ __forceinline__ uint32_t smem_u32(const void* p) {
    uint32_t a;
    asm("{ .reg .u64 t; cvta.to.shared.u64 t, %1; cvt.u32.u64 %0, t; }"
        : "=r"(a) : "l"(p));
    return a;
}

__global__ __launch_bounds__(THREADS)
void svd_predict_kernel(const int2* __restrict__ ui,
                        const float4* __restrict__ pu4,   // [N_USERS][16]
                        const float4* __restrict__ qi4,   // [N_ITEMS][16]
                        const float* __restrict__ bu,
                        const float* __restrict__ bi,
                        const float* __restrict__ gm,
                        float* __restrict__ out_pred,
                        float* __restrict__ out_feat)     // [BATCH][128]
{
    __shared__ __align__(128) float stage[WARPS_PER_CTA][WARP_TILE_FLOATS]; // 16KB

    const int warp_l = threadIdx.x >> 5;                 // warp in CTA
    const int warp   = blockIdx.x * WARPS_PER_CTA + warp_l;
    const int lane   = threadIdx.x & 31;
    const int half   = lane >> 4;     // 0 or 1
    const int g      = lane & 15;     // lane within half-warp

    const int r0 = warp * ROWS_PER_WARP + half * 2;      // this half's rows
    const int r1 = r0 + 1;

    const int2 id0 = __ldg(&ui[r0]);
    const int2 id1 = __ldg(&ui[r1]);

    // 4 independent 16B gathers per thread (64B in flight), registers.
    const float4 a0 = __ldg(pu4 + (size_t)id0.x * 16 + g);
    const float4 b0 = __ldg(qi4 + (size_t)id0.y * 16 + g);
    const float4 a1 = __ldg(pu4 + (size_t)id1.x * 16 + g);
    const float4 b1 = __ldg(qi4 + (size_t)id1.y * 16 + g);

    float d0 = a0.x * b0.x + a0.y * b0.y + a0.z * b0.z + a0.w * b0.w;
    float d1 = a1.x * b1.x + a1.y * b1.y + a1.z * b1.z + a1.w * b1.w;

    #pragma unroll
    for (int off = 8; off; off >>= 1) {
        d0 += __shfl_xor_sync(0xFFFFFFFFu, d0, off);
        d1 += __shfl_xor_sync(0xFFFFFFFFu, d1, off);
    }

    // Stage features in smem (smem crossbar, not L1tex): layout identical to
    // the global feature rows for this warp's 4 rows.
    float4* wstage = reinterpret_cast<float4*>(stage[warp_l]);
    // local rows: half*2 and half*2+1; each row = 32 float4.
    float4* s0 = wstage + (half * 2) * 32;
    float4* s1 = s0 + 32;
    s0[g]      = a0;
    s0[g + 16] = b0;
    s1[g]      = a1;
    s1[g + 16] = b1;

    // Predictions (tiny STG.32, keep streaming).
    if (g == 0) {
        const float base = __ldg(gm);
        float p0 = base + __ldg(&bu[id0.x]) + __ldg(&bi[id0.y]) + d0;
        float p1 = base + __ldg(&bu[id1.x]) + __ldg(&bi[id1.y]) + d1;
        __stcs(&out_pred[r0], fminf(fmaxf(p0, 1.0f), 5.0f));
        __stcs(&out_pred[r1], fminf(fmaxf(p1, 1.0f), 5.0f));
    }

    // One 2KB bulk store per warp: smem -> contiguous global feature rows.
    asm volatile("fence.proxy.async.shared::cta;" ::: "memory");
    __syncwarp();
    if (lane == 0) {
        float* dst = out_feat + (size_t)(warp * ROWS_PER_WARP) * ROW_FLOATS;
        asm volatile(
            "cp.async.bulk.global.shared::cta.bulk_group [%0], [%1], %2;"
            :: "l"(dst), "r"(smem_u32(stage[warp_l])),
               "r"((uint32_t)(WARP_TILE_FLOATS * 4)) : "memory");
        asm volatile("cp.async.bulk.commit_group;\n"
                     "cp.async.bulk.wait_group.read 0;\n" ::: "memory");
    }
}

extern "C" void kernel_launch(void* const* d_in, const int* in_sizes, int n_in,
                              void* d_out, int out_size)
{
    const int2*   ui  = (const int2*)  d_in[0];
    const float4* pu4 = (const float4*)d_in[1];
    const float4* qi4 = (const float4*)d_in[2];
    const float*  bu  = (const float*) d_in[3];
    const float*  bi  = (const float*) d_in[4];
    const float*  gm  = (const float*) d_in[5];

    float* out_pred = (float*)d_out;               // [BATCH]
    float* out_feat = out_pred + BATCH;            // [BATCH][128]

    const int warps  = BATCH / ROWS_PER_WARP;      // 32768
    const int blocks = warps / WARPS_PER_CTA;      // 4096
    svd_predict_kernel<<<blocks, THREADS>>>(ui, pu4, qi4, bu, bi, gm,
                                            out_pred, out_feat);
}

// round 15
// speedup vs baseline: 1.0677x; 1.0677x over previous
#include <cuda_runtime.h>
#include <cstdint>

// SVD predict: R2 register gathers + smem staging + ONE 16KB TMA bulk
// feature store per CTA. Feature writes leave the L1tex wavefront queue
// (STG.128 -> STS.128 + cp.async.bulk), freeing queue capacity for the
// latency-bound gather reads.
//
// Inputs (metadata order):
//   d_in[0] user_item  int32  [131072, 2]
//   d_in[1] pu         f32    [1000000, 64]
//   d_in[2] qi         f32    [500000, 64]
//   d_in[3] bu         f32    [1000000]
//   d_in[4] bi         f32    [500000]
//   d_in[5] global_mean f32   [1]
// Output: float32 [131072 predict] ++ [131072 x 128 features]

#define BATCH 131072
#define ROWS_PER_WARP 4
#define WARPS_PER_CTA 8
#define THREADS 256
#define ROWS_PER_CTA (ROWS_PER_WARP * WARPS_PER_CTA)    // 32
#define ROW_FLOATS 128                                  // [p(64) | q(64)]
#define TILE_FLOATS (ROWS_PER_CTA * ROW_FLOATS)         // 4096 floats = 16 KB

__device__ __forceinline__ uint32_t smem_u32(const void* p) {
    uint32_t a;
    asm("{ .reg .u64 t; cvta.to.shared.u64 t, %1; cvt.u32.u64 %0, t; }"
        : "=r"(a) : "l"(p));
    return a;
}

__global__ __launch_bounds__(THREADS)
void svd_predict_kernel(const int2* __restrict__ ui,
                        const float4* __restrict__ pu4,   // [N_USERS][16]
                        const float4* __restrict__ qi4,   // [N_ITEMS][16]
                        const float* __restrict__ bu,
                        const float* __restrict__ bi,
                        const float* __restrict__ gm,
                        float* __restrict__ out_pred,
                        float* __restrict__ out_feat)     // [BATCH][128]
{
    __shared__ __align__(128) float tile[TILE_FLOATS];    // 16 KB

    const int warp_l = threadIdx.x >> 5;
    const int lane   = threadIdx.x & 31;
    const int half   = lane >> 4;     // 0 or 1
    const int g      = lane & 15;     // lane within half-warp

    const int warp = blockIdx.x * WARPS_PER_CTA + warp_l;
    const int r0   = warp * ROWS_PER_WARP + half * 2;     // global row
    const int r1   = r0 + 1;
    const int lr0  = warp_l * ROWS_PER_WARP + half * 2;   // row within CTA tile
    const int lr1  = lr0 + 1;

    const int2 id0 = __ldg(&ui[r0]);
    const int2 id1 = __ldg(&ui[r1]);

    // 4 independent 16B gathers per thread (64B in flight), registers.
    const float4 a0 = __ldg(pu4 + (size_t)id0.x * 16 + g);
    const float4 b0 = __ldg(qi4 + (size_t)id0.y * 16 + g);
    const float4 a1 = __ldg(pu4 + (size_t)id1.x * 16 + g);
    const float4 b1 = __ldg(qi4 + (size_t)id1.y * 16 + g);

    float d0 = a0.x * b0.x + a0.y * b0.y + a0.z * b0.z + a0.w * b0.w;
    float d1 = a1.x * b1.x + a1.y * b1.y + a1.z * b1.z + a1.w * b1.w;

    #pragma unroll
    for (int off = 8; off; off >>= 1) {
        d0 += __shfl_xor_sync(0xFFFFFFFFu, d0, off);
        d1 += __shfl_xor_sync(0xFFFFFFFFu, d1, off);
    }

    // Stage features in smem, layout identical to global feature rows.
    float4* t4 = reinterpret_cast<float4*>(tile);
    float4* s0 = t4 + lr0 * 32;
    float4* s1 = t4 + lr1 * 32;
    s0[g]      = a0;
    s0[g + 16] = b0;
    s1[g]      = a1;
    s1[g + 16] = b1;

    // Predictions (tiny, streaming).
    if (g == 0) {
        const float base = __ldg(gm);
        float p0 = base + __ldg(&bu[id0.x]) + __ldg(&bi[id0.y]) + d0;
        float p1 = base + __ldg(&bu[id1.x]) + __ldg(&bi[id1.y]) + d1;
        __stcs(&out_pred[r0], fminf(fmaxf(p0, 1.0f), 5.0f));
        __stcs(&out_pred[r1], fminf(fmaxf(p1, 1.0f), 5.0f));
    }

    __syncthreads();

    // One 16 KB bulk store per CTA: smem -> contiguous global feature rows.
    if (threadIdx.x == 0) {
        asm volatile("fence.proxy.async.shared::cta;" ::: "memory");
        float* dst = out_feat + (size_t)blockIdx.x * TILE_FLOATS;
        asm volatile(
            "cp.async.bulk.global.shared::cta.bulk_group [%0], [%1], %2;"
            :: "l"(dst), "r"(smem_u32(tile)),
               "r"((uint32_t)(TILE_FLOATS * 4)) : "memory");
        asm volatile("cp.async.bulk.commit_group;\n"
                     "cp.async.bulk.wait_group.read 0;\n" ::: "memory");
    }
}

extern "C" void kernel_launch(void* const* d_in, const int* in_sizes, int n_in,
                              void* d_out, int out_size)
{
    const int2*   ui  = (const int2*)  d_in[0];
    const float4* pu4 = (const float4*)d_in[1];
    const float4* qi4 = (const float4*)d_in[2];
    const float*  bu  = (const float*) d_in[3];
    const float*  bi  = (const float*) d_in[4];
    const float*  gm  = (const float*) d_in[5];

    float* out_pred = (float*)d_out;               // [BATCH]
    float* out_feat = out_pred + BATCH;            // [BATCH][128]

    const int blocks = BATCH / ROWS_PER_CTA;       // 4096
    svd_predict_kernel<<<blocks, THREADS>>>(ui, pu4, qi4, bu, bi, gm,
                                            out_pred, out_feat);
}

// round 16
// speedup vs baseline: 1.1484x; 1.0755x over previous
#include <cuda_runtime.h>
#include <cstdint>

// SVD predict: 4 rows/warp, octet layout, 256-bit (v8.b32) gathers.
// Doubles bytes-in-flight per L1tex queue entry vs LDG.128 variants.
//
// Inputs (metadata order):
//   d_in[0] user_item  int32  [131072, 2]
//   d_in[1] pu         f32    [1000000, 64]
//   d_in[2] qi         f32    [500000, 64]
//   d_in[3] bu         f32    [1000000]
//   d_in[4] bi         f32    [500000]
//   d_in[5] global_mean f32   [1]
// Output: float32 [131072 predict] ++ [131072 x 128 features]

#define BATCH 131072
#define ROWS_PER_WARP 4

// 32B load: 8 consecutive floats.
__device__ __forceinline__ void ld256(const float* p, float4& lo, float4& hi) {
    uint32_t r0,r1,r2,r3,r4,r5,r6,r7;
    asm("ld.global.nc.v8.b32 {%0,%1,%2,%3,%4,%5,%6,%7}, [%8];"
        : "=r"(r0),"=r"(r1),"=r"(r2),"=r"(r3),
          "=r"(r4),"=r"(r5),"=r"(r6),"=r"(r7)
        : "l"(p));
    lo.x = __uint_as_float(r0); lo.y = __uint_as_float(r1);
    lo.z = __uint_as_float(r2); lo.w = __uint_as_float(r3);
    hi.x = __uint_as_float(r4); hi.y = __uint_as_float(r5);
    hi.z = __uint_as_float(r6); hi.w = __uint_as_float(r7);
}

__global__ __launch_bounds__(256)
void svd_predict_kernel(const int2* __restrict__ ui,
                        const float* __restrict__ pu,
                        const float* __restrict__ qi,
                        const float* __restrict__ bu,
                        const float* __restrict__ bi,
                        const float* __restrict__ gm,
                        float* __restrict__ out_pred,
                        float4* __restrict__ out_feat4)   // [BATCH][32]
{
    const int warp = (blockIdx.x * blockDim.x + threadIdx.x) >> 5;
    const int lane = threadIdx.x & 31;
    const int o    = lane >> 3;       // octet 0..3 -> row within warp
    const int g    = lane & 7;        // 32B chunk within row

    const int r = warp * ROWS_PER_WARP + o;

    // ids: lanes 0..3 fetch, broadcast to octets.
    int2 myid = make_int2(0, 0);
    if (lane < ROWS_PER_WARP) myid = __ldg(&ui[warp * ROWS_PER_WARP + lane]);
    const int uid = __shfl_sync(0xFFFFFFFFu, myid.x, o);
    const int iid = __shfl_sync(0xFFFFFFFFu, myid.y, o);

    // Two 32B gathers per thread (p chunk, q chunk of the same row).
    float4 pl, ph, ql, qh;
    ld256(pu + (size_t)uid * 64 + g * 8, pl, ph);
    ld256(qi + (size_t)iid * 64 + g * 8, ql, qh);

    float d = pl.x * ql.x + pl.y * ql.y + pl.z * ql.z + pl.w * ql.w
            + ph.x * qh.x + ph.y * qh.y + ph.z * qh.z + ph.w * qh.w;

    // Reduce within octet: all 4 rows in parallel, 3 steps.
    #pragma unroll
    for (int off = 4; off; off >>= 1)
        d += __shfl_xor_sync(0xFFFFFFFFu, d, off);

    // Feature stores: row r = [p(64) | q(64)] floats; thread covers
    // float4 indices 2g,2g+1 (p) and 16+2g,16+2g+1 (q). Full 128B lines.
    float4* frow = out_feat4 + (size_t)r * 32;
    __stcs(frow + 2 * g,          pl);
    __stcs(frow + 2 * g + 1,      ph);
    __stcs(frow + 16 + 2 * g,     ql);
    __stcs(frow + 16 + 2 * g + 1, qh);

    // Predictions: lane g==0 of each octet owns its row's dot.
    if (g == 0) {
        float pr = __ldg(gm) + __ldg(&bu[uid]) + __ldg(&bi[iid]) + d;
        __stcs(&out_pred[r], fminf(fmaxf(pr, 1.0f), 5.0f));
    }
}

extern "C" void kernel_launch(void* const* d_in, const int* in_sizes, int n_in,
                              void* d_out, int out_size)
{
    const int2*  ui = (const int2*) d_in[0];
    const float* pu = (const float*)d_in[1];
    const float* qi = (const float*)d_in[2];
    const float* bu = (const float*)d_in[3];
    const float* bi = (const float*)d_in[4];
    const float* gm = (const float*)d_in[5];

    float*  out_pred  = (float*)d_out;                 // [BATCH]
    float4* out_feat4 = (float4*)(out_pred + BATCH);   // [BATCH][32]

    const int threads = 256;                                  // 8 warps
    const int warps   = BATCH / ROWS_PER_WARP;                // 32768
    const int blocks  = warps / (threads / 32);               // 4096
    svd_predict_kernel<<<blocks, threads>>>(ui, pu, qi, bu, bi, gm,
                                            out_pred, out_feat4);
}

// round 17
// speedup vs baseline: 1.3022x; 1.1340x over previous
#include <cuda_runtime.h>
#include <cstdint>

// SVD predict, 4 rows/warp (R2 shape) + micro-opts. R2-class kernels sit at
// ~91% of the practical chip-wide LTS byte cap (~6.9 TB/s); this round only
// trims instruction/serialization overhead, not traffic.
//
// Inputs (metadata order):
//   d_in[0] user_item  int32  [131072, 2]
//   d_in[1] pu         f32    [1000000, 64]
//   d_in[2] qi         f32    [500000, 64]
//   d_in[3] bu         f32    [1000000]
//   d_in[4] bi         f32    [500000]
//   d_in[5] global_mean f32   [1]
// Output: float32 [131072 predict] ++ [131072 x 128 features]

#define BATCH 131072
#define ROWS_PER_WARP 4

__global__ __launch_bounds__(256)
void svd_predict_kernel(const int4* __restrict__ ui2,    // [BATCH/2] 2 rows/elt
                        const float4* __restrict__ pu4,  // [N_USERS][16]
                        const float4* __restrict__ qi4,  // [N_ITEMS][16]
                        const float* __restrict__ bu,
                        const float* __restrict__ bi,
                        const float* __restrict__ gm,
                        float* __restrict__ out_pred,
                        float4* __restrict__ out_feat4)  // [BATCH][32]
{
    const int warp = (blockIdx.x * blockDim.x + threadIdx.x) >> 5;
    const int lane = threadIdx.x & 31;
    const int half = lane >> 4;      // 0 or 1
    const int g    = lane & 15;      // lane within half-warp

    const int r0 = warp * ROWS_PER_WARP + half * 2;
    const int r1 = r0 + 1;

    // One broadcast int4 per half-warp: ids of rows r0 (x,y) and r1 (z,w).
    const int4 ids = __ldg(&ui2[r0 >> 1]);

    // Bias loads issued unconditionally (broadcast within half-warp) so their
    // latency overlaps the embedding gathers instead of following the reduce.
    const float bu0 = __ldg(&bu[ids.x]);
    const float bi0 = __ldg(&bi[ids.y]);
    const float bu1 = __ldg(&bu[ids.z]);
    const float bi1 = __ldg(&bi[ids.w]);
    const float base = __ldg(gm);

    // 4 independent 16B gathers per thread (64B in flight).
    const float4 a0 = __ldg(pu4 + (size_t)ids.x * 16 + g);
    const float4 b0 = __ldg(qi4 + (size_t)ids.y * 16 + g);
    const float4 a1 = __ldg(pu4 + (size_t)ids.z * 16 + g);
    const float4 b1 = __ldg(qi4 + (size_t)ids.w * 16 + g);

    float d0 = a0.x * b0.x + a0.y * b0.y + a0.z * b0.z + a0.w * b0.w;
    float d1 = a1.x * b1.x + a1.y * b1.y + a1.z * b1.z + a1.w * b1.w;

    #pragma unroll
    for (int off = 8; off; off >>= 1) {
        d0 += __shfl_xor_sync(0xFFFFFFFFu, d0, off);
        d1 += __shfl_xor_sync(0xFFFFFFFFu, d1, off);
    }

    // Streaming feature stores: [p | q] per row, full 128B lines.
    float4* f0 = out_feat4 + (size_t)r0 * 32;
    float4* f1 = out_feat4 + (size_t)r1 * 32;
    __stcs(f0 + g,      a0);
    __stcs(f0 + g + 16, b0);
    __stcs(f1 + g,      a1);
    __stcs(f1 + g + 16, b1);

    // Parallel pred stores: lane 0 -> r0, lane 1 -> r1 (both have d0,d1).
    if (g == 0) {
        float p0 = base + bu0 + bi0 + d0;
        __stcs(&out_pred[r0], fminf(fmaxf(p0, 1.0f), 5.0f));
    } else if (g == 1) {
        float p1 = base + bu1 + bi1 + d1;
        __stcs(&out_pred[r1], fminf(fmaxf(p1, 1.0f), 5.0f));
    }
}

extern "C" void kernel_launch(void* const* d_in, const int* in_sizes, int n_in,
                              void* d_out, int out_size)
{
    const int4*   ui2 = (const int4*)  d_in[0];
    const float4* pu4 = (const float4*)d_in[1];
    const float4* qi4 = (const float4*)d_in[2];
    const float*  bu  = (const float*) d_in[3];
    const float*  bi  = (const float*) d_in[4];
    const float*  gm  = (const float*) d_in[5];

    float*  out_pred  = (float*)d_out;                 // [BATCH]
    float4* out_feat4 = (float4*)(out_pred + BATCH);   // [BATCH][32]

    const int threads = 256;                                  // 8 warps
    const int warps   = BATCH / ROWS_PER_WARP;                // 32768
    const int blocks  = warps / (threads / 32);               // 4096
    svd_predict_kernel<<<blocks, threads>>>(ui2, pu4, qi4, bu, bi, gm,
                                            out_pred, out_feat4);
}